// round 9
// baseline (speedup 1.0000x reference)
#include <cuda_runtime.h>

#define C 1000
#define D 128
#define STRIDE 2048          // max rows per class bin (max expected ~1130)
#define BIN_PAD 8            // guard entries after the last bin (spec-load safety)
#define CP 256               // cursor padding: 1KB per class
#define MOM 0.95f

#define SCAT_THREADS 256
#define SCAT_ILP 8           // 8 independent atomic+store chains per thread

#define RED_THREADS 256      // 8 warps
#define RED_WARPS 8
#define UNROLL 4

// Static scratch (allocation-free rule): zero-initialized at module load.
__device__ int  g_cursor[C * CP];                 // per-class cursor, 1KB stride
__device__ int2 g_bins[C * STRIDE + BIN_PAD];     // packed (row_index, weight_bits)

// ---------------------------------------------------------------------------
// Pass 1: bin rows by label. Batched: load 8 labels+weights, issue all 8
// cursor atomics back-to-back (8 outstanding ATOMG chains), then all 8
// predicated bin stores. Latency-bound -> maximize per-thread MLP.
// ---------------------------------------------------------------------------
__global__ void __launch_bounds__(SCAT_THREADS) scatter_kernel(
    const int*   __restrict__ labels,
    const float* __restrict__ weights,
    int n)
{
    int t    = blockIdx.x * blockDim.x + threadIdx.x;
    int base = t * SCAT_ILP;
    if (base >= n) return;

    int   lab[SCAT_ILP];
    float w[SCAT_ILP];

    if (base + SCAT_ILP <= n) {
        int4   l4a = *reinterpret_cast<const int4*>(labels + base);
        int4   l4b = *reinterpret_cast<const int4*>(labels + base + 4);
        float4 w4a = *reinterpret_cast<const float4*>(weights + base);
        float4 w4b = *reinterpret_cast<const float4*>(weights + base + 4);
        lab[0] = l4a.x; lab[1] = l4a.y; lab[2] = l4a.z; lab[3] = l4a.w;
        lab[4] = l4b.x; lab[5] = l4b.y; lab[6] = l4b.z; lab[7] = l4b.w;
        w[0] = w4a.x; w[1] = w4a.y; w[2] = w4a.z; w[3] = w4a.w;
        w[4] = w4b.x; w[5] = w4b.y; w[6] = w4b.z; w[7] = w4b.w;
    } else {
#pragma unroll
        for (int k = 0; k < SCAT_ILP; k++) {
            int r  = base + k;
            lab[k] = (r < n) ? labels[r]  : -1;
            w[k]   = (r < n) ? weights[r] : 0.0f;
        }
    }

    // Phase A: issue all atomics (independent -> 8 outstanding)
    int pos[SCAT_ILP];
#pragma unroll
    for (int k = 0; k < SCAT_ILP; k++) {
        int l  = lab[k];
        bool v = (l >= 0 && l < C);
        pos[k] = v ? atomicAdd(&g_cursor[l * CP], 1) : STRIDE;
    }

    // Phase B: predicated bin stores
#pragma unroll
    for (int k = 0; k < SCAT_ILP; k++) {
        if (pos[k] < STRIDE) {
            int2 e;
            e.x = base + k;
            e.y = __float_as_int(w[k]);
            g_bins[(size_t)lab[k] * STRIDE + pos[k]] = e;
        }
    }
}

// ---------------------------------------------------------------------------
// Pass 2 (UNCHANGED from the 88.4us/78.6%-DRAM version): one CTA per class.
// Gather rows (contiguous 512B each), accumulate in registers (atomic-free),
// cross-warp reduce in SMEM, fused EMA epilogue. Single long loop per CTA.
// ---------------------------------------------------------------------------
__global__ void __launch_bounds__(RED_THREADS) reduce_kernel(
    const float* __restrict__ feats,
    const float* __restrict__ proto,
    float*       __restrict__ out)
{
    __shared__ float s_acc[RED_WARPS][D];
    __shared__ float s_w[RED_WARPS];

    const int c = blockIdx.x;
    int cnt = g_cursor[c * CP];
    if (cnt > STRIDE) cnt = STRIDE;

    const int warp = threadIdx.x >> 5;
    const int lane = threadIdx.x & 31;

    float4 acc  = make_float4(0.f, 0.f, 0.f, 0.f);
    float  wsum = 0.f;

    const int2*   bin = g_bins + (size_t)c * STRIDE;
    const float4* f4  = reinterpret_cast<const float4*>(feats);

    // Warps stride in UNROLL-row batches; batched loads give MLP ~ 4 rows/warp.
    for (int base = warp * UNROLL; base < cnt; base += RED_WARPS * UNROLL) {
        int2 e[UNROLL];
#pragma unroll
        for (int u = 0; u < UNROLL; u++) {
            int r = base + u;
            e[u] = (r < cnt) ? bin[r] : make_int2(0, 0);  // w=0 -> harmless
        }
        float4 f[UNROLL];
#pragma unroll
        for (int u = 0; u < UNROLL; u++)
            f[u] = f4[(size_t)e[u].x * (D / 4) + lane];   // coalesced 512B row
#pragma unroll
        for (int u = 0; u < UNROLL; u++) {
            float w = __int_as_float(e[u].y);
            acc.x += w * f[u].x;
            acc.y += w * f[u].y;
            acc.z += w * f[u].z;
            acc.w += w * f[u].w;
            wsum  += w;
        }
    }

    // per-warp partials -> SMEM
    reinterpret_cast<float4*>(s_acc[warp])[lane] = acc;   // STS.128
    if (lane == 0) s_w[warp] = wsum;                      // all lanes equal
    __syncthreads();

    // final reduce + fused EMA epilogue (threads 0..127 = columns)
    const int col = threadIdx.x;
    if (col < D) {
        float tot = 0.f, ws = 0.f;
#pragma unroll
        for (int k = 0; k < RED_WARPS; k++) { tot += s_acc[k][col]; ws += s_w[k]; }
        float p   = proto[c * D + col];
        float vec = tot / fmaxf(ws, 1e-8f);
        out[c * D + col] = (ws > 0.f) ? (MOM * p + (1.0f - MOM) * vec) : p;
    }

    // reset cursor for the next graph replay (zero-init covers call #1;
    // all readers passed the __syncthreads above)
    if (threadIdx.x == 0) g_cursor[c * CP] = 0;
}

extern "C" void kernel_launch(void* const* d_in, const int* in_sizes, int n_in,
                              void* d_out, int out_size)
{
    const float* feats   = (const float*)d_in[0];
    const int*   labels  = (const int*)  d_in[1];
    const float* weights = (const float*)d_in[2];
    const float* proto   = (const float*)d_in[3];
    float*       out     = (float*)d_out;

    const int n = in_sizes[1];  // labels element count == N

    const int scat_grid = (n + SCAT_THREADS * SCAT_ILP - 1) / (SCAT_THREADS * SCAT_ILP);
    scatter_kernel<<<scat_grid, SCAT_THREADS>>>(labels, weights, n);
    reduce_kernel<<<C, RED_THREADS>>>(feats, proto, out);
}